// round 2
// baseline (speedup 1.0000x reference)
#include <cuda_runtime.h>
#include <cuda_fp16.h>

#define N_NODES 50000
#define N_EDGES 1600000
#define NCLS    48
#define NH2     24            // half2 per row
#define NSTEP   10
#define SCAN_B  1024
#define NBLK    ((N_NODES + SCAN_B - 1) / SCAN_B)   // 49

// ---------------- device scratch (static, no runtime allocation) -------------
__device__ float   g_deg[N_NODES];
__device__ int     g_cnt[N_NODES];
__device__ int     g_off[N_NODES + 1];
__device__ int     g_cur[N_NODES];
__device__ int2    g_edge[N_EDGES];                  // (src, weight-as-int)
__device__ __half2 g_hh[2][(size_t)N_NODES * NH2];   // fp16 feature buffers
__device__ int     g_bsums[64];

// ---------------- preprocessing kernels --------------------------------------
__global__ void zero_kernel() {
    int i = blockIdx.x * blockDim.x + threadIdx.x;
    if (i < N_NODES) { g_deg[i] = 0.0f; g_cnt[i] = 0; }
}

__global__ void deg_kernel(const int* __restrict__ row, const int* __restrict__ col,
                           const float* __restrict__ attr) {
    int e = blockIdx.x * blockDim.x + threadIdx.x;
    if (e < N_EDGES) {
        atomicAdd(&g_deg[row[e]], attr[e]);
        atomicAdd(&g_cnt[col[e]], 1);
    }
}

__global__ void scan1_kernel() {
    __shared__ int sh[SCAN_B];
    int tid = threadIdx.x;
    int i = blockIdx.x * SCAN_B + tid;
    int v = (i < N_NODES) ? g_cnt[i] : 0;
    sh[tid] = v;
    __syncthreads();
    for (int d = 1; d < SCAN_B; d <<= 1) {
        int t = (tid >= d) ? sh[tid - d] : 0;
        __syncthreads();
        sh[tid] += t;
        __syncthreads();
    }
    if (i < N_NODES) g_off[i] = sh[tid] - v;
    if (tid == SCAN_B - 1) g_bsums[blockIdx.x] = sh[tid];
}

__global__ void scan2_kernel() {
    __shared__ int sh[64];
    int tid = threadIdx.x;
    int v = (tid < NBLK) ? g_bsums[tid] : 0;
    sh[tid] = v;
    __syncthreads();
    for (int d = 1; d < 64; d <<= 1) {
        int t = (tid >= d) ? sh[tid - d] : 0;
        __syncthreads();
        sh[tid] += t;
        __syncthreads();
    }
    if (tid < NBLK) g_bsums[tid] = sh[tid] - v;
}

__global__ void scan3_kernel() {
    int i = blockIdx.x * blockDim.x + threadIdx.x;
    if (i < N_NODES) {
        int o = g_off[i] + g_bsums[i / SCAN_B];
        g_off[i] = o;
        g_cur[i] = o;
    }
    if (i == 0) g_off[N_NODES] = N_EDGES;
}

// bucket edges by destination; precompute row-normalized weight; packed 8B store
__global__ void fill_kernel(const int* __restrict__ row, const int* __restrict__ col,
                            const float* __restrict__ attr) {
    int e = blockIdx.x * blockDim.x + threadIdx.x;
    if (e < N_EDGES) {
        int r = row[e];
        int c = col[e];
        float w = attr[e] / fmaxf(g_deg[r], 1e-12f);
        int p = atomicAdd(&g_cur[c], 1);
        g_edge[p] = make_int2(r, __float_as_int(w));
    }
}

// one-hot init into g_hh[0] (half2 writes)
__global__ void h0_kernel(const int* __restrict__ target) {
    int idx = blockIdx.x * blockDim.x + threadIdx.x;
    if (idx < N_NODES * NH2) {
        int n  = idx / NH2;
        int c2 = (idx - n * NH2) * 2;
        int t  = target[n];
        g_hh[0][idx] = __floats2half2_rn(t == c2 ? 1.0f : 0.0f,
                                         t == c2 + 1 ? 1.0f : 0.0f);
    }
}

// ---------------- main propagation step: one warp per destination node -------
// lanes 0..23 each own classes (2l, 2l+1); per edge: one 96B coalesced row read
__global__ void gather_kernel(const float* __restrict__ Wm, float* __restrict__ out, int s) {
    int gwarp = (blockIdx.x * blockDim.x + threadIdx.x) >> 5;
    int lane  = threadIdx.x & 31;
    if (gwarp >= N_NODES) return;

    const __half2* __restrict__ hin  = g_hh[s & 1];
    __half2*       __restrict__ hout = g_hh[(s & 1) ^ 1];

    int beg = g_off[gwarp];
    int end = g_off[gwarp + 1];
    bool act = (lane < NH2);

    float ax0 = 0.f, ay0 = 0.f, ax1 = 0.f, ay1 = 0.f;
    float ax2 = 0.f, ay2 = 0.f, ax3 = 0.f, ay3 = 0.f;

    int j = beg;
    for (; j + 4 <= end; j += 4) {
        int2 e0 = g_edge[j], e1 = g_edge[j + 1], e2 = g_edge[j + 2], e3 = g_edge[j + 3];
        if (act) {
            float2 x0 = __half22float2(hin[(size_t)e0.x * NH2 + lane]);
            float2 x1 = __half22float2(hin[(size_t)e1.x * NH2 + lane]);
            float2 x2 = __half22float2(hin[(size_t)e2.x * NH2 + lane]);
            float2 x3 = __half22float2(hin[(size_t)e3.x * NH2 + lane]);
            float w0 = __int_as_float(e0.y), w1 = __int_as_float(e1.y);
            float w2 = __int_as_float(e2.y), w3 = __int_as_float(e3.y);
            ax0 = fmaf(w0, x0.x, ax0); ay0 = fmaf(w0, x0.y, ay0);
            ax1 = fmaf(w1, x1.x, ax1); ay1 = fmaf(w1, x1.y, ay1);
            ax2 = fmaf(w2, x2.x, ax2); ay2 = fmaf(w2, x2.y, ay2);
            ax3 = fmaf(w3, x3.x, ax3); ay3 = fmaf(w3, x3.y, ay3);
        }
    }
    for (; j < end; j++) {
        int2 e = g_edge[j];
        if (act) {
            float2 x = __half22float2(hin[(size_t)e.x * NH2 + lane]);
            float w = __int_as_float(e.y);
            ax0 = fmaf(w, x.x, ax0); ay0 = fmaf(w, x.y, ay0);
        }
    }

    if (act) {
        float accx = (ax0 + ax1) + (ax2 + ax3);
        float accy = (ay0 + ay1) + (ay2 + ay3);

        hout[(size_t)gwarp * NH2 + lane] = __floats2half2_rn(accx, accy);

        float2 o;
        o.x = accx * Wm[(2 * lane) * NSTEP + s];
        o.y = accy * Wm[(2 * lane + 1) * NSTEP + s];
        float2* op = (float2*)(out + (size_t)gwarp * NCLS) + lane;
        if (s != 0) { float2 p = *op; o.x += p.x; o.y += p.y; }
        *op = o;
    }
}

// ---------------- launch ------------------------------------------------------
extern "C" void kernel_launch(void* const* d_in, const int* in_sizes, int n_in,
                              void* d_out, int out_size) {
    const int*   ei     = (const int*)d_in[0];     // [2, E]
    const int*   row    = ei;
    const int*   col    = ei + N_EDGES;
    const float* attr   = (const float*)d_in[1];   // [E]
    const int*   target = (const int*)d_in[2];     // [N]
    const float* Wm     = (const float*)d_in[3];   // [C, S]
    float*       out    = (float*)d_out;           // [N, C]

    const int TB = 256;
    int nblk_nodes = (N_NODES + TB - 1) / TB;
    int nblk_edges = (N_EDGES + TB - 1) / TB;
    int nblk_h0    = (N_NODES * NH2 + TB - 1) / TB;

    zero_kernel<<<nblk_nodes, TB>>>();
    deg_kernel<<<nblk_edges, TB>>>(row, col, attr);
    scan1_kernel<<<NBLK, SCAN_B>>>();
    scan2_kernel<<<1, 64>>>();
    scan3_kernel<<<nblk_nodes, TB>>>();
    fill_kernel<<<nblk_edges, TB>>>(row, col, attr);
    h0_kernel<<<nblk_h0, TB>>>(target);

    int nblk_gather = (N_NODES + 7) / 8;   // 8 warps/block, 1 node/warp
    for (int s = 0; s < NSTEP; s++) {
        gather_kernel<<<nblk_gather, TB>>>(Wm, out, s);
    }
}